// round 13
// baseline (speedup 1.0000x reference)
#include <cuda_runtime.h>
#include <math.h>

#define B_  256
#define T_  512
#define D_  512
#define H_  1024
#define BH  (B_ * H_)
#define TBH ((size_t)T_ * B_ * H_)

#define GRID 256
#define NTHR 256

typedef unsigned long long ull;

// Scratch. g_G layout: [gate][t][b][h], gate 0=z, 1=r, 2=h_cand. Biases folded.
static __device__ float g_G[3 * TBH];
static __device__ float g_h [BH];
static __device__ float g_z [BH];
static __device__ float g_rh[BH];
static __device__ float g_PA[8u * 256 * 2048];    // A split-K partials (16MB)
static __device__ float g_PB[16u * 256 * 1024];   // B split-K partials (16MB)
static __device__ unsigned g_bar;

static __device__ __forceinline__ float sigmoidf_(float x) {
    return 1.0f / (1.0f + expf(-x));
}

// Packed fp32x2 FMA (Blackwell; PTX-only — ptxas never auto-fuses).
static __device__ __forceinline__ ull fma2_(ull a, ull b, ull c) {
    ull d;
    asm("fma.rn.f32x2 %0, %1, %2, %3;" : "=l"(d) : "l"(a), "l"(b), "l"(c));
    return d;
}
static __device__ __forceinline__ ull dup2_(float x) {
    ull d;
    asm("mov.b64 %0, {%1, %2};" : "=l"(d) : "f"(x), "f"(x));
    return d;
}
static __device__ __forceinline__ float2 unpack2_(ull v) {
    float2 r;
    asm("mov.b64 {%0, %1}, %2;" : "=f"(r.x), "=f"(r.y) : "l"(v));
    return r;
}

// Monotonic-counter grid barrier (counter reset by xproj_kernel each replay).
static __device__ __forceinline__ void grid_barrier(unsigned target) {
    __syncthreads();
    if (threadIdx.x == 0) {
        __threadfence();
        atomicAdd(&g_bar, 1u);
        volatile unsigned* p = &g_bar;
        while (*p < target) { __nanosleep(32); }
    }
    __syncthreads();
}

// ---------------------------------------------------------------------------
// Phase 1: G[gate][t][b][:] = x[b][t][:] @ W_gate + bias_gate  (unchanged)
// ---------------------------------------------------------------------------
__global__ __launch_bounds__(256) void xproj_kernel(
    const float* __restrict__ x,
    const float* __restrict__ Wz, const float* __restrict__ Wr, const float* __restrict__ Wh,
    const float* __restrict__ bz, const float* __restrict__ br, const float* __restrict__ bh)
{
    if (blockIdx.x == 0 && blockIdx.y == 0 && blockIdx.z == 0 && threadIdx.x == 0)
        g_bar = 0u;

    __shared__ float As[2][8][132];
    __shared__ float Bs[2][8][128];

    const int gate = blockIdx.z;
    const float* Wm   = (gate == 0) ? Wz : (gate == 1) ? Wr : Wh;
    const float* bias = (gate == 0) ? bz : (gate == 1) ? br : bh;

    const int m0 = blockIdx.y * 128;
    const int n0 = blockIdx.x * 128;
    const int tid = threadIdx.x;

    const int arow  = tid >> 1;
    const int acol  = (tid & 1) * 4;
    const int brow  = tid >> 5;
    const int bcol4 = (tid & 31) * 4;
    const int ty = tid >> 4;
    const int tx = tid & 15;

    ull acc2[4][8];
    #pragma unroll
    for (int i = 0; i < 4; i++)
        #pragma unroll
        for (int j = 0; j < 8; j++) acc2[i][j] = 0ull;

    float4 pa = *(const float4*)(x + (size_t)(m0 + arow) * D_ + acol);
    float4 pb = *(const float4*)(Wm + (size_t)brow * H_ + n0 + bcol4);

    for (int s = 0; s < D_ / 8; s++) {
        const int buf = s & 1;
        As[buf][acol + 0][arow] = pa.x;
        As[buf][acol + 1][arow] = pa.y;
        As[buf][acol + 2][arow] = pa.z;
        As[buf][acol + 3][arow] = pa.w;
        *(float4*)&Bs[buf][brow][bcol4] = pb;
        __syncthreads();

        if (s < D_ / 8 - 1) {
            int kk = (s + 1) * 8;
            pa = *(const float4*)(x + (size_t)(m0 + arow) * D_ + kk + acol);
            pb = *(const float4*)(Wm + (size_t)(kk + brow) * H_ + n0 + bcol4);
        }

        #pragma unroll
        for (int k = 0; k < 8; k++) {
            ulonglong2 ap0 = *(const ulonglong2*)&As[buf][k][ty * 8];
            ulonglong2 ap1 = *(const ulonglong2*)&As[buf][k][ty * 8 + 4];
            float4 bv0 = *(const float4*)&Bs[buf][k][tx * 8];
            float4 bv1 = *(const float4*)&Bs[buf][k][tx * 8 + 4];
            ull bd[8];
            bd[0] = dup2_(bv0.x); bd[1] = dup2_(bv0.y);
            bd[2] = dup2_(bv0.z); bd[3] = dup2_(bv0.w);
            bd[4] = dup2_(bv1.x); bd[5] = dup2_(bv1.y);
            bd[6] = dup2_(bv1.z); bd[7] = dup2_(bv1.w);
            #pragma unroll
            for (int j = 0; j < 8; j++) {
                acc2[0][j] = fma2_(ap0.x, bd[j], acc2[0][j]);
                acc2[1][j] = fma2_(ap0.y, bd[j], acc2[1][j]);
                acc2[2][j] = fma2_(ap1.x, bd[j], acc2[2][j]);
                acc2[3][j] = fma2_(ap1.y, bd[j], acc2[3][j]);
            }
        }
    }

    float accf[8][8];
    #pragma unroll
    for (int mp = 0; mp < 4; mp++)
        #pragma unroll
        for (int j = 0; j < 8; j++) {
            float2 v = unpack2_(acc2[mp][j]);
            accf[2 * mp + 0][j] = v.x;
            accf[2 * mp + 1][j] = v.y;
        }

    float* Gg = g_G + (size_t)gate * TBH;
    float bb[8];
    #pragma unroll
    for (int j = 0; j < 8; j++) bb[j] = bias[n0 + tx * 8 + j];

    #pragma unroll
    for (int i = 0; i < 8; i++) {
        int m    = m0 + ty * 8 + i;
        int bidx = m >> 9;
        int tidx = m & 511;
        float* row = Gg + ((size_t)tidx * B_ + bidx) * H_ + n0 + tx * 8;
        #pragma unroll
        for (int j = 0; j < 8; j++) row[j] = accf[i][j] + bb[j];
    }
}

// ---------------------------------------------------------------------------
// 128x128 partial-GEMM tile, K-chunk = kblocks*16, FFMA2 8x8/thread.
// A (mutable, __ldcg): rows stride H_.  B (weights, __ldg): rows stride H_.
// ---------------------------------------------------------------------------
static __device__ __forceinline__ void gemm128_tile(
    const float* __restrict__ A, const float* __restrict__ B,
    float* __restrict__ outp, int outStride, int kblocks,
    float (*As)[16][136], float (*Bs)[16][128], int tid)
{
    const int arow = tid >> 1;          // 0..127
    const int ac8  = (tid & 1) * 8;     // 0 or 8
    const int brow = tid >> 4;          // 0..15
    const int bc8  = (tid & 15) * 8;    // 0..120
    const int ty   = tid >> 4;          // 0..15
    const int tx   = tid & 15;          // 0..15

    ull acc2[4][8];
    #pragma unroll
    for (int i = 0; i < 4; i++)
        #pragma unroll
        for (int j = 0; j < 8; j++) acc2[i][j] = 0ull;

    float4 pa0 = __ldcg((const float4*)(A + (size_t)arow * H_ + ac8));
    float4 pa1 = __ldcg((const float4*)(A + (size_t)arow * H_ + ac8 + 4));
    float4 pb0 = __ldg ((const float4*)(B + (size_t)brow * H_ + bc8));
    float4 pb1 = __ldg ((const float4*)(B + (size_t)brow * H_ + bc8 + 4));

    for (int s = 0; s < kblocks; s++) {
        const int buf = s & 1;
        As[buf][ac8 + 0][arow] = pa0.x;
        As[buf][ac8 + 1][arow] = pa0.y;
        As[buf][ac8 + 2][arow] = pa0.z;
        As[buf][ac8 + 3][arow] = pa0.w;
        As[buf][ac8 + 4][arow] = pa1.x;
        As[buf][ac8 + 5][arow] = pa1.y;
        As[buf][ac8 + 6][arow] = pa1.z;
        As[buf][ac8 + 7][arow] = pa1.w;
        *(float4*)&Bs[buf][brow][bc8]     = pb0;
        *(float4*)&Bs[buf][brow][bc8 + 4] = pb1;
        __syncthreads();

        if (s + 1 < kblocks) {
            int kk = (s + 1) * 16;
            pa0 = __ldcg((const float4*)(A + (size_t)arow * H_ + kk + ac8));
            pa1 = __ldcg((const float4*)(A + (size_t)arow * H_ + kk + ac8 + 4));
            pb0 = __ldg ((const float4*)(B + (size_t)(kk + brow) * H_ + bc8));
            pb1 = __ldg ((const float4*)(B + (size_t)(kk + brow) * H_ + bc8 + 4));
        }

        #pragma unroll
        for (int k = 0; k < 16; k++) {
            ulonglong2 a01 = *(const ulonglong2*)&As[buf][k][ty * 8];
            ulonglong2 a23 = *(const ulonglong2*)&As[buf][k][ty * 8 + 4];
            float4 b0 = *(const float4*)&Bs[buf][k][tx * 8];
            float4 b1 = *(const float4*)&Bs[buf][k][tx * 8 + 4];
            ull bd[8];
            bd[0] = dup2_(b0.x); bd[1] = dup2_(b0.y);
            bd[2] = dup2_(b0.z); bd[3] = dup2_(b0.w);
            bd[4] = dup2_(b1.x); bd[5] = dup2_(b1.y);
            bd[6] = dup2_(b1.z); bd[7] = dup2_(b1.w);
            #pragma unroll
            for (int j = 0; j < 8; j++) {
                acc2[0][j] = fma2_(a01.x, bd[j], acc2[0][j]);
                acc2[1][j] = fma2_(a01.y, bd[j], acc2[1][j]);
                acc2[2][j] = fma2_(a23.x, bd[j], acc2[2][j]);
                acc2[3][j] = fma2_(a23.y, bd[j], acc2[3][j]);
            }
        }
    }

    // Epilogue: write partials, row-pair at a time.
    #pragma unroll
    for (int p = 0; p < 4; p++) {
        float r0[8], r1[8];
        #pragma unroll
        for (int j = 0; j < 8; j++) {
            float2 v = unpack2_(acc2[p][j]);
            r0[j] = v.x; r1[j] = v.y;
        }
        float* o0 = outp + (size_t)(ty * 8 + 2 * p + 0) * outStride + tx * 8;
        float* o1 = outp + (size_t)(ty * 8 + 2 * p + 1) * outStride + tx * 8;
        *(float4*)(o0)     = make_float4(r0[0], r0[1], r0[2], r0[3]);
        *(float4*)(o0 + 4) = make_float4(r0[4], r0[5], r0[6], r0[7]);
        *(float4*)(o1)     = make_float4(r1[0], r1[1], r1[2], r1[3]);
        *(float4*)(o1 + 4) = make_float4(r1[4], r1[5], r1[6], r1[7]);
    }
}

// ---------------------------------------------------------------------------
// Persistent recurrence: 256 CTAs x 256 thr (2 CTAs/SM via reg cap 128).
//  A-gemm : 2M x 16N x 8K CTAs, 128x128x128 partials -> g_PA
//  A-red  : sum 8 partials + sigmoid -> g_z / g_rh
//  B-gemm : 2M x 8N x 16K CTAs, 128x128x64 partials -> g_PB
//  B-red  : sum 16 partials + tanh + h update -> g_h
// ---------------------------------------------------------------------------
__global__ __launch_bounds__(NTHR, 2) void gru_persistent(
    const float* __restrict__ Uz, const float* __restrict__ Ur,
    const float* __restrict__ U,  float* __restrict__ out)
{
    __shared__ float As[2][16][136];
    __shared__ float Bs[2][16][128];

    const int cta = blockIdx.x;
    const int tid = threadIdx.x;
    unsigned bcount = 0;

    // ---- step 0: h = sigmoid(Gz[0]) * tanh(Gh[0])  (h0 = 0) ----
    {
        size_t idx = (size_t)(cta * NTHR + tid) * 4;   // 256 float4 per CTA
        float4 gz = *(const float4*)&g_G[idx];
        float4 gh = *(const float4*)&g_G[2 * TBH + idx];
        float4 h;
        h.x = sigmoidf_(gz.x) * tanhf(gh.x);
        h.y = sigmoidf_(gz.y) * tanhf(gh.y);
        h.z = sigmoidf_(gz.z) * tanhf(gh.z);
        h.w = sigmoidf_(gz.w) * tanhf(gh.w);
        *(float4*)&g_h[idx] = h;
    }
    bcount++; grid_barrier(bcount * GRID);

    // A-gemm decomposition: 8K x 2M x 16N
    const int ksA = cta >> 5;              // 0..7
    const int remA = cta & 31;
    const int msA = remA >> 4;             // 0..1
    const int nsA = remA & 15;             // 0..15
    const float* BsrcA = (nsA < 8) ? (Uz + nsA * 128) : (Ur + (nsA - 8) * 128);

    // B-gemm decomposition: 16K x 2M x 8N
    const int ksB = cta >> 4;              // 0..15
    const int remB = cta & 15;
    const int msB = remB >> 3;             // 0..1
    const int nsB = remB & 7;              // 0..7

    for (int t = 1; t < T_; t++) {
        // ===== A-gemm: partial (h @ [Uz|Ur]), K-chunk 128 ==================
        gemm128_tile(
            g_h + (size_t)msA * 128 * H_ + ksA * 128,
            BsrcA + (size_t)ksA * 128 * H_,
            g_PA + ((size_t)ksA * 256 + msA * 128) * 2048 + nsA * 128,
            2048, 8, As, Bs, tid);
        bcount++; grid_barrier(bcount * GRID);

        // ===== A-red: z = sig(sum+Gz), rh = sig(sum+Gr)*h ===================
        {
            const float4* PA4 = (const float4*)g_PA;
            #pragma unroll
            for (int j = 0; j < 2; j++) {
                int idx4 = cta * 512 + j * 256 + tid;
                int m  = idx4 >> 9;          // 512 float4 per 2048-row
                int c4 = idx4 & 511;
                float4 s = __ldcg(PA4 + idx4);
                #pragma unroll
                for (int ks = 1; ks < 8; ks++) {
                    float4 p = __ldcg(PA4 + idx4 + ks * 131072);
                    s.x += p.x; s.y += p.y; s.z += p.z; s.w += p.w;
                }
                if (c4 < 256) {
                    int n = c4 * 4;
                    float4 g = *(const float4*)(g_G + (size_t)t * BH + m * H_ + n);
                    float4 z;
                    z.x = sigmoidf_(s.x + g.x);
                    z.y = sigmoidf_(s.y + g.y);
                    z.z = sigmoidf_(s.z + g.z);
                    z.w = sigmoidf_(s.w + g.w);
                    *(float4*)&g_z[m * H_ + n] = z;
                } else {
                    int n = (c4 - 256) * 4;
                    float4 g = *(const float4*)(g_G + TBH + (size_t)t * BH + m * H_ + n);
                    float4 h = __ldcg((const float4*)&g_h[m * H_ + n]);
                    float4 rh;
                    rh.x = sigmoidf_(s.x + g.x) * h.x;
                    rh.y = sigmoidf_(s.y + g.y) * h.y;
                    rh.z = sigmoidf_(s.z + g.z) * h.z;
                    rh.w = sigmoidf_(s.w + g.w) * h.w;
                    *(float4*)&g_rh[m * H_ + n] = rh;
                }
            }
        }
        bcount++; grid_barrier(bcount * GRID);

        // ===== B-gemm: partial (rh @ U), K-chunk 64 =========================
        gemm128_tile(
            g_rh + (size_t)msB * 128 * H_ + ksB * 64,
            U + (size_t)ksB * 64 * H_ + nsB * 128,
            g_PB + ((size_t)ksB * 256 + msB * 128) * 1024 + nsB * 128,
            1024, 4, As, Bs, tid);
        bcount++; grid_barrier(bcount * GRID);

        // ===== B-red: h = (1-z)h + z*tanh(sum+Gh) ===========================
        {
            const float4* PB4 = (const float4*)g_PB;
            int idx4 = cta * 256 + tid;      // 65536 float4 over 256 CTAs
            int m  = idx4 >> 8;              // 256 float4 per 1024-row
            int n  = (idx4 & 255) * 4;
            float4 s = __ldcg(PB4 + idx4);
            #pragma unroll
            for (int ks = 1; ks < 16; ks++) {
                float4 p = __ldcg(PB4 + idx4 + ks * 65536);
                s.x += p.x; s.y += p.y; s.z += p.z; s.w += p.w;
            }
            float4 g = *(const float4*)(g_G + 2 * TBH + (size_t)t * BH + m * H_ + n);
            float4 z = __ldcg((const float4*)&g_z[m * H_ + n]);
            float4 h = __ldcg((const float4*)&g_h[m * H_ + n]);
            float4 hn;
            hn.x = (1.0f - z.x) * h.x + z.x * tanhf(s.x + g.x);
            hn.y = (1.0f - z.y) * h.y + z.y * tanhf(s.y + g.y);
            hn.z = (1.0f - z.z) * h.z + z.z * tanhf(s.z + g.z);
            hn.w = (1.0f - z.w) * h.w + z.w * tanhf(s.w + g.w);
            *(float4*)&g_h[m * H_ + n] = hn;
        }
        bcount++; grid_barrier(bcount * GRID);
    }

    // ---- copy out ----
    {
        size_t idx = (size_t)(cta * NTHR + tid) * 4;
        float4 h = __ldcg((const float4*)&g_h[idx]);
        *(float4*)&out[idx] = h;
    }
}

// ---------------------------------------------------------------------------
extern "C" void kernel_launch(void* const* d_in, const int* in_sizes, int n_in,
                              void* d_out, int out_size)
{
    const float* x  = (const float*)d_in[0];  // [B,T,D]
    const float* W  = (const float*)d_in[1];  // [D,H]
    const float* U  = (const float*)d_in[2];  // [H,H]
    const float* Wz = (const float*)d_in[3];
    const float* Uz = (const float*)d_in[4];
    const float* Wr = (const float*)d_in[5];
    const float* Ur = (const float*)d_in[6];
    const float* b  = (const float*)d_in[7];
    const float* bz = (const float*)d_in[8];
    const float* br = (const float*)d_in[9];

    (void)in_sizes; (void)n_in; (void)out_size;

    // Node 1: input projections (biases folded) + barrier-counter reset.
    dim3 g1(H_ / 128, (B_ * T_) / 128, 3);
    xproj_kernel<<<g1, 256>>>(x, Wz, Wr, W, bz, br, b);

    // Node 2: entire recurrence, one persistent kernel (2 CTAs/SM).
    gru_persistent<<<GRID, NTHR>>>(Uz, Ur, U, (float*)d_out);
}